// round 11
// baseline (speedup 1.0000x reference)
#include <cuda_runtime.h>
#include <cuda_fp16.h>
#include <cstdint>

#define BB 4
#define SS 2048
#define DD 1024
#define MTOT (BB*SS)   // 8192

// Static device scratch
__device__ __half g_X [(long)MTOT*DD];
__device__ __half g_Y [(long)MTOT*DD];
__device__ __half g_Z [(long)MTOT*DD];
__device__ __half g_W [3][(long)DD*DD];
__device__ __half g_Q [(long)MTOT*DD];
__device__ __half g_K [(long)MTOT*DD];
__device__ __half g_Vt[(long)BB*DD*SS];    // V transposed: [b][d][s]
__device__ __half g_P [(long)BB*SS*SS];    // exp(scores) fp16 (unnormalized)
__device__ float  g_RS[MTOT];              // per-row sums of exp

// Linear padded smem layout: 128 halves/row data + 8 halves pad = 144B stride.
// Rows advance 36 banks (= +4 mod 32): any 8 consecutive rows are
// bank-conflict-free for ldmatrix phases and 16B stores. No XOR swizzle.
#define ROWB     144u
#define TILE_B   (128u * ROWB)     // 18432 B per operand tile
#define STG      (2u * TILE_B)     // 36864 B (A + B)
#define STAGES   3
#define SMEMSZ   (STAGES * STG)    // 110592 B -> 2 CTAs/SM

// ---------------------------------------------------------------------------
// helpers
// ---------------------------------------------------------------------------
__device__ __forceinline__ uint32_t smem_u32(const void* p) {
    uint32_t a;
    asm("{ .reg .u64 t; cvta.to.shared.u64 t, %1; cvt.u32.u64 %0, t; }"
        : "=r"(a) : "l"(p));
    return a;
}
__device__ __forceinline__ void cp16(uint32_t s, const void* g) {
    asm volatile("cp.async.cg.shared.global [%0], [%1], 16;" :: "r"(s), "l"(g));
}

#define LDSM4(r, addr) \
    asm volatile("ldmatrix.sync.aligned.m8n8.x4.shared.b16 {%0,%1,%2,%3}, [%4];" \
        : "=r"((r)[0]), "=r"((r)[1]), "=r"((r)[2]), "=r"((r)[3]) : "r"(addr))

#define MMA_F16(c, a, b0, b1) \
    asm volatile("mma.sync.aligned.m16n8k16.row.col.f32.f16.f16.f32 " \
        "{%0,%1,%2,%3}, {%4,%5,%6,%7}, {%8,%9}, {%0,%1,%2,%3};" \
        : "+f"((c)[0]), "+f"((c)[1]), "+f"((c)[2]), "+f"((c)[3]) \
        : "r"((a)[0]), "r"((a)[1]), "r"((a)[2]), "r"((a)[3]), "r"(b0), "r"(b1))

// ---------------------------------------------------------------------------
// Single fused fp32->fp16 conversion for X,Y,Z,Wq,Wk,Wv + RS zeroing.
// Flat block ranges: [0,4096) X, [4096,8192) Y, [8192,12288) Z,
// [12288,12800) Wq, [12800,13312) Wk, [13312,13824) Wv.
// Each thread converts 8 elements.
// ---------------------------------------------------------------------------
__global__ void cvt_all(const float4* __restrict__ x, const float4* __restrict__ y,
                        const float4* __restrict__ z, const float4* __restrict__ wq,
                        const float4* __restrict__ wk, const float4* __restrict__ wv,
                        __half* __restrict__ X, __half* __restrict__ Y,
                        __half* __restrict__ Z, __half* __restrict__ W,
                        float* __restrict__ rs)
{
    const int b = blockIdx.x;
    const float4* in;
    __half* out;
    long base;
    if (b < 4096)       { in = x;  out = X; base = (long)b * 2048; }
    else if (b < 8192)  { in = y;  out = Y; base = (long)(b - 4096) * 2048; }
    else if (b < 12288) { in = z;  out = Z; base = (long)(b - 8192) * 2048; }
    else if (b < 12800) { in = wq; out = W;                       base = (long)(b - 12288) * 2048; }
    else if (b < 13312) { in = wk; out = W + (long)DD * DD;       base = (long)(b - 12800) * 2048; }
    else                { in = wv; out = W + 2 * (long)DD * DD;   base = (long)(b - 13312) * 2048; }

    if (b < 32) rs[b * 256 + threadIdx.x] = 0.0f;

    const long e = base + (long)threadIdx.x * 8;
    float4 a0 = in[e >> 2], a1 = in[(e >> 2) + 1];
    __half2 h[4];
    h[0] = __floats2half2_rn(a0.x, a0.y);
    h[1] = __floats2half2_rn(a0.z, a0.w);
    h[2] = __floats2half2_rn(a1.x, a1.y);
    h[3] = __floats2half2_rn(a1.z, a1.w);
    *(uint4*)(out + e) = *(uint4*)h;
}

// ---------------------------------------------------------------------------
// Shared fp16 NT GEMM mainloop, rolling fragment prefetch, LINEAR 144B rows.
// acc = A[128,K] @ B[128,K]^T; K contiguous; 3-stage cp.async; 8 warps (2x4),
// warp tile 64x32; fp32 accumulate.
// ---------------------------------------------------------------------------
__device__ __forceinline__ void mainloop_h(
    const __half* __restrict__ A, const __half* __restrict__ B,
    int K, int lda, int ldb, uint32_t sbase,
    int tid, int lane, int wm, int wn, float acc[4][4][4])
{
    const __half* ga[4];
    const __half* gb[4];
    uint32_t sw[4];
#pragma unroll
    for (int i = 0; i < 4; i++) {
        const int idx = i * 256 + tid;
        const int row = idx >> 3;
        const int c   = idx & 7;
        sw[i] = (uint32_t)row * ROWB + (uint32_t)c * 16u;
        ga[i] = A + (long)row * lda + c * 8;
        gb[i] = B + (long)row * ldb + c * 8;
    }

    auto issue = [&](int kt, int st) {
        const uint32_t s0 = sbase + (uint32_t)st * STG;
#pragma unroll
        for (int i = 0; i < 4; i++) cp16(s0 + sw[i], ga[i] + (long)kt * 64);
#pragma unroll
        for (int i = 0; i < 4; i++) cp16(s0 + TILE_B + sw[i], gb[i] + (long)kt * 64);
        asm volatile("cp.async.commit_group;" ::: "memory");
    };

    const int r16 = lane & 15;
    const uint32_t hi16 = (uint32_t)(lane >> 4) * 16u;   // k half-select bytes
    uint32_t aOff[4], bOff[2];
#pragma unroll
    for (int mt = 0; mt < 4; mt++)
        aOff[mt] = (uint32_t)(wm * 64 + mt * 16 + r16) * ROWB + hi16;
#pragma unroll
    for (int p = 0; p < 2; p++)
        bOff[p] = TILE_B + (uint32_t)(wn * 32 + p * 16 + r16) * ROWB + hi16;

    const int KT = K >> 6;
#pragma unroll
    for (int s = 0; s < STAGES - 1; s++) issue(s, s);

    for (int kt = 0; kt < KT; kt++) {
        asm volatile("cp.async.wait_group %0;" :: "n"(STAGES - 2));
        __syncthreads();

        const int pf = kt + STAGES - 1;
        if (pf < KT) issue(pf, pf % STAGES);
        else asm volatile("cp.async.commit_group;" ::: "memory");

        const uint32_t base = sbase + (uint32_t)(kt % STAGES) * STG;

        uint32_t af[2][4];      // ping-pong by mt parity
        uint32_t bf[2][2][4];   // ping-pong by kc parity

        // preload kc=0 fragments: both B blocks + first A block
        LDSM4(bf[0][0], base + bOff[0]);
        LDSM4(bf[0][1], base + bOff[1]);
        LDSM4(af[0],    base + aOff[0]);

#pragma unroll
        for (int kc = 0; kc < 4; kc++) {
            const uint32_t kb  = (uint32_t)kc * 32u;
            const uint32_t kbn = kb + 32u;
#pragma unroll
            for (int mt = 0; mt < 4; mt++) {
                if (mt < 3) {
                    LDSM4(af[(mt + 1) & 1], base + aOff[mt + 1] + kb);
                } else if (kc < 3) {
                    LDSM4(bf[(kc + 1) & 1][0], base + bOff[0] + kbn);
                    LDSM4(bf[(kc + 1) & 1][1], base + bOff[1] + kbn);
                    LDSM4(af[0],               base + aOff[0] + kbn);
                }
#pragma unroll
                for (int nt = 0; nt < 4; nt++)
                    MMA_F16(acc[mt][nt], af[mt & 1],
                            bf[kc & 1][nt >> 1][nt & 1],
                            bf[kc & 1][nt >> 1][(nt & 1) + 2]);
            }
        }
    }
}

// ---------------------------------------------------------------------------
// Merged QKV projection: z = blockIdx.z selects (input, W, bias, output).
// z==2 (V) stores transposed per batch: Vt[(b*DD + n)*SS + s].
// ---------------------------------------------------------------------------
__global__ __launch_bounds__(256, 2)
void gemm_proj(const __half* __restrict__ Ax, const __half* __restrict__ Ay,
               const __half* __restrict__ Az, const __half* __restrict__ W,
               const float* __restrict__ b0, const float* __restrict__ b1,
               const float* __restrict__ b2,
               __half* __restrict__ Qo, __half* __restrict__ Ko,
               __half* __restrict__ Vt)
{
    extern __shared__ __align__(1024) char smem[];
    const uint32_t sbase = smem_u32(smem);
    const int tid  = threadIdx.x;
    const int lane = tid & 31;
    const int wid  = tid >> 5;
    const int wm   = wid & 1;
    const int wn   = wid >> 1;
    const int bm   = blockIdx.y * 128;
    const int bn   = blockIdx.x * 128;
    const int z    = blockIdx.z;

    const __half* A = (z == 0) ? Ax : (z == 1) ? Ay : Az;
    const __half* B = W + (long)z * DD * DD;
    const float* bias = (z == 0) ? b0 : (z == 1) ? b1 : b2;

    float acc[4][4][4];
#pragma unroll
    for (int mt = 0; mt < 4; mt++)
#pragma unroll
        for (int nt = 0; nt < 4; nt++)
#pragma unroll
            for (int i = 0; i < 4; i++) acc[mt][nt][i] = 0.0f;

    mainloop_h(A + (long)bm * DD, B + (long)bn * DD, DD, DD, DD,
               sbase, tid, lane, wm, wn, acc);

    const int g  = lane >> 2;
    const int tg = lane & 3;
#pragma unroll
    for (int mt = 0; mt < 4; mt++) {
#pragma unroll
        for (int nt = 0; nt < 4; nt++) {
            const int n = bn + wn * 32 + nt * 8 + tg * 2;
            float2 bv = *(const float2*)(bias + n);
#pragma unroll
            for (int h = 0; h < 2; h++) {
                const int m = bm + wm * 64 + mt * 16 + g + h * 8;
                const float v0 = acc[mt][nt][h * 2 + 0] + bv.x;
                const float v1 = acc[mt][nt][h * 2 + 1] + bv.y;
                if (z == 2) {
                    const int b = m >> 11;
                    const int s = m & (SS - 1);
                    const long o = ((long)b * DD + n) * SS + s;
                    Vt[o]      = __float2half_rn(v0);
                    Vt[o + SS] = __float2half_rn(v1);
                } else {
                    __half* C = (z == 0) ? Qo : Ko;
                    *(__half2*)(C + (long)m * DD + n) = __floats2half2_rn(v0, v1);
                }
            }
        }
    }
}

// ---------------------------------------------------------------------------
// Scores: P = exp(Q @ K^T / 32) (fp16, unnormalized) + atomic row sums.
// ---------------------------------------------------------------------------
__global__ __launch_bounds__(256, 2)
void gemm_scores(const __half* __restrict__ Q, const __half* __restrict__ Kb,
                 __half* __restrict__ P, float* __restrict__ RS)
{
    extern __shared__ __align__(1024) char smem[];
    const uint32_t sbase = smem_u32(smem);
    const int tid  = threadIdx.x;
    const int lane = tid & 31;
    const int wid  = tid >> 5;
    const int wm   = wid & 1;
    const int wn   = wid >> 1;
    const int bm   = blockIdx.y * 128;
    const int bn   = blockIdx.x * 128;
    const long bz  = blockIdx.z;

    const __half* A = Q  + bz * SS * DD + (long)bm * DD;
    const __half* B = Kb + bz * SS * DD + (long)bn * DD;
    __half* Pb = P + bz * (long)SS * SS;
    float* rs = RS + bz * SS;

    float acc[4][4][4];
#pragma unroll
    for (int mt = 0; mt < 4; mt++)
#pragma unroll
        for (int nt = 0; nt < 4; nt++)
#pragma unroll
            for (int i = 0; i < 4; i++) acc[mt][nt][i] = 0.0f;

    mainloop_h(A, B, DD, DD, DD, sbase, tid, lane, wm, wn, acc);

    const int g  = lane >> 2;
    const int tg = lane & 3;
#pragma unroll
    for (int mt = 0; mt < 4; mt++) {
        float s0 = 0.0f, s1 = 0.0f;
        const int m0 = bm + wm * 64 + mt * 16 + g;
#pragma unroll
        for (int nt = 0; nt < 4; nt++) {
            const int n = bn + wn * 32 + nt * 8 + tg * 2;
            const float e00 = __expf(acc[mt][nt][0] * 0.03125f);
            const float e01 = __expf(acc[mt][nt][1] * 0.03125f);
            const float e10 = __expf(acc[mt][nt][2] * 0.03125f);
            const float e11 = __expf(acc[mt][nt][3] * 0.03125f);
            s0 += e00 + e01;
            s1 += e10 + e11;
            *(__half2*)(Pb + (long)m0 * SS + n)       = __floats2half2_rn(e00, e01);
            *(__half2*)(Pb + (long)(m0 + 8) * SS + n) = __floats2half2_rn(e10, e11);
        }
        s0 += __shfl_xor_sync(~0u, s0, 1);
        s0 += __shfl_xor_sync(~0u, s0, 2);
        s1 += __shfl_xor_sync(~0u, s1, 1);
        s1 += __shfl_xor_sync(~0u, s1, 2);
        if (tg == 0) {
            atomicAdd(&rs[m0],     s0);
            atomicAdd(&rs[m0 + 8], s1);
        }
    }
}

// ---------------------------------------------------------------------------
// PV: out = (P @ Vt^T) / rowsum  (fp32 out)
// ---------------------------------------------------------------------------
__global__ __launch_bounds__(256, 2)
void gemm_pv(const __half* __restrict__ P, const __half* __restrict__ Vt,
             const float* __restrict__ RS, float* __restrict__ O)
{
    extern __shared__ __align__(1024) char smem[];
    const uint32_t sbase = smem_u32(smem);
    const int tid  = threadIdx.x;
    const int lane = tid & 31;
    const int wid  = tid >> 5;
    const int wm   = wid & 1;
    const int wn   = wid >> 1;
    const int bm   = blockIdx.y * 128;
    const int bn   = blockIdx.x * 128;
    const long bz  = blockIdx.z;

    const __half* A = P  + bz * (long)SS * SS + (long)bm * SS;
    const __half* B = Vt + bz * (long)DD * SS + (long)bn * SS;
    const float* rs = RS + bz * SS;
    float* C = O + bz * (long)SS * DD;

    float acc[4][4][4];
#pragma unroll
    for (int mt = 0; mt < 4; mt++)
#pragma unroll
        for (int nt = 0; nt < 4; nt++)
#pragma unroll
            for (int i = 0; i < 4; i++) acc[mt][nt][i] = 0.0f;

    mainloop_h(A, B, SS, SS, SS, sbase, tid, lane, wm, wn, acc);

    const int g  = lane >> 2;
    const int tg = lane & 3;
#pragma unroll
    for (int mt = 0; mt < 4; mt++) {
        const int m0 = bm + wm * 64 + mt * 16 + g;
        const float i0 = 1.0f / __ldg(&rs[m0]);
        const float i1 = 1.0f / __ldg(&rs[m0 + 8]);
#pragma unroll
        for (int nt = 0; nt < 4; nt++) {
            const int n = bn + wn * 32 + nt * 8 + tg * 2;
            float2 v0, v1;
            v0.x = acc[mt][nt][0] * i0;
            v0.y = acc[mt][nt][1] * i0;
            v1.x = acc[mt][nt][2] * i1;
            v1.y = acc[mt][nt][3] * i1;
            *(float2*)(C + (long)m0 * DD + n)       = v0;
            *(float2*)(C + (long)(m0 + 8) * DD + n) = v1;
        }
    }
}

extern "C" void kernel_launch(void* const* d_in, const int* in_sizes, int n_in,
                              void* d_out, int out_size)
{
    const float* x  = (const float*)d_in[0];
    const float* y  = (const float*)d_in[1];
    const float* z  = (const float*)d_in[2];
    const float* Wq = (const float*)d_in[3];
    const float* bq = (const float*)d_in[4];
    const float* Wk = (const float*)d_in[5];
    const float* bk = (const float*)d_in[6];
    const float* Wv = (const float*)d_in[7];
    const float* bv = (const float*)d_in[8];
    float* out = (float*)d_out;

    void *pX, *pY, *pZ, *pW, *pQ, *pK, *pV, *pP, *pRS;
    cudaGetSymbolAddress(&pX,  g_X);
    cudaGetSymbolAddress(&pY,  g_Y);
    cudaGetSymbolAddress(&pZ,  g_Z);
    cudaGetSymbolAddress(&pW,  g_W);
    cudaGetSymbolAddress(&pQ,  g_Q);
    cudaGetSymbolAddress(&pK,  g_K);
    cudaGetSymbolAddress(&pV,  g_Vt);
    cudaGetSymbolAddress(&pP,  g_P);
    cudaGetSymbolAddress(&pRS, g_RS);
    __half* X  = (__half*)pX;
    __half* Y  = (__half*)pY;
    __half* Z  = (__half*)pZ;
    __half* W  = (__half*)pW;
    __half* Q  = (__half*)pQ;
    __half* Kb = (__half*)pK;
    __half* Vt = (__half*)pV;
    __half* P  = (__half*)pP;
    float*  RS = (float*)pRS;

    cudaFuncSetAttribute(gemm_proj,   cudaFuncAttributeMaxDynamicSharedMemorySize, SMEMSZ);
    cudaFuncSetAttribute(gemm_scores, cudaFuncAttributeMaxDynamicSharedMemorySize, SMEMSZ);
    cudaFuncSetAttribute(gemm_pv,     cudaFuncAttributeMaxDynamicSharedMemorySize, SMEMSZ);

    // 0) one fused conversion pass (X,Y,Z,Wq,Wk,Wv) + RS zeroing
    cvt_all<<<13824, 256>>>((const float4*)x, (const float4*)y, (const float4*)z,
                            (const float4*)Wq, (const float4*)Wk, (const float4*)Wv,
                            X, Y, Z, W, RS);
    // 1) merged QKV projections (V transposed)
    {
        dim3 g1(DD / 128, MTOT / 128, 3);
        gemm_proj<<<g1, 256, SMEMSZ>>>(X, Y, Z, W, bq, bk, bv, Q, Kb, Vt);
    }
    // 2) P = exp(Q K^T / 32), row sums via atomics
    {
        dim3 g2(SS / 128, SS / 128, BB);
        gemm_scores<<<g2, 256, SMEMSZ>>>(Q, Kb, P, RS);
    }
    // 3) out = (P @ Vt^T) / rowsum
    {
        dim3 g3(DD / 128, SS / 128, BB);
        gemm_pv<<<g3, 256, SMEMSZ>>>(P, Vt, RS, out);
    }
}

// round 12
// speedup vs baseline: 1.1581x; 1.1581x over previous
#include <cuda_runtime.h>
#include <cuda_fp16.h>
#include <cstdint>

#define BB 4
#define SS 2048
#define DD 1024
#define MTOT (BB*SS)   // 8192

// Static device scratch
__device__ __half g_X [(long)MTOT*DD];
__device__ __half g_Y [(long)MTOT*DD];
__device__ __half g_Z [(long)MTOT*DD];
__device__ __half g_W [3][(long)DD*DD];
__device__ __half g_Q [(long)MTOT*DD];
__device__ __half g_K [(long)MTOT*DD];
__device__ __half g_Vt[(long)BB*DD*SS];    // V transposed: [b][d][s]
__device__ __half g_P [(long)BB*SS*SS];    // exp(scores) fp16 (unnormalized)
__device__ float  g_RS[MTOT];              // per-row sums of exp

// ---------------------------------------------------------------------------
// helpers
// ---------------------------------------------------------------------------
__device__ __forceinline__ uint32_t smem_u32(const void* p) {
    uint32_t a;
    asm("{ .reg .u64 t; cvta.to.shared.u64 t, %1; cvt.u32.u64 %0, t; }"
        : "=r"(a) : "l"(p));
    return a;
}
__device__ __forceinline__ void cp16(uint32_t s, const void* g) {
    asm volatile("cp.async.cg.shared.global [%0], [%1], 16;" :: "r"(s), "l"(g));
}

#define LDSM4(r, addr) \
    asm volatile("ldmatrix.sync.aligned.m8n8.x4.shared.b16 {%0,%1,%2,%3}, [%4];" \
        : "=r"((r)[0]), "=r"((r)[1]), "=r"((r)[2]), "=r"((r)[3]) : "r"(addr))

#define MMA_F16(c, a, b0, b1) \
    asm volatile("mma.sync.aligned.m16n8k16.row.col.f32.f16.f16.f32 " \
        "{%0,%1,%2,%3}, {%4,%5,%6,%7}, {%8,%9}, {%0,%1,%2,%3};" \
        : "+f"((c)[0]), "+f"((c)[1]), "+f"((c)[2]), "+f"((c)[3]) \
        : "r"((a)[0]), "r"((a)[1]), "r"((a)[2]), "r"((a)[3]), "r"(b0), "r"(b1))

// ---------------------------------------------------------------------------
// Single fused fp32->fp16 conversion for X,Y,Z,Wq,Wk,Wv + RS zeroing.
// Flat block ranges: [0,4096) X, [4096,8192) Y, [8192,12288) Z,
// [12288,12800) Wq, [12800,13312) Wk, [13312,13824) Wv. 8 elems/thread.
// ---------------------------------------------------------------------------
__global__ void cvt_all(const float4* __restrict__ x, const float4* __restrict__ y,
                        const float4* __restrict__ z, const float4* __restrict__ wq,
                        const float4* __restrict__ wk, const float4* __restrict__ wv,
                        __half* __restrict__ X, __half* __restrict__ Y,
                        __half* __restrict__ Z, __half* __restrict__ W,
                        float* __restrict__ rs)
{
    const int b = blockIdx.x;
    const float4* in;
    __half* out;
    long base;
    if (b < 4096)       { in = x;  out = X; base = (long)b * 2048; }
    else if (b < 8192)  { in = y;  out = Y; base = (long)(b - 4096) * 2048; }
    else if (b < 12288) { in = z;  out = Z; base = (long)(b - 8192) * 2048; }
    else if (b < 12800) { in = wq; out = W;                       base = (long)(b - 12288) * 2048; }
    else if (b < 13312) { in = wk; out = W + (long)DD * DD;       base = (long)(b - 12800) * 2048; }
    else                { in = wv; out = W + 2 * (long)DD * DD;   base = (long)(b - 13312) * 2048; }

    if (b < 32) rs[b * 256 + threadIdx.x] = 0.0f;

    const long e = base + (long)threadIdx.x * 8;
    float4 a0 = in[e >> 2], a1 = in[(e >> 2) + 1];
    __half2 h[4];
    h[0] = __floats2half2_rn(a0.x, a0.y);
    h[1] = __floats2half2_rn(a0.z, a0.w);
    h[2] = __floats2half2_rn(a1.x, a1.y);
    h[3] = __floats2half2_rn(a1.z, a1.w);
    *(uint4*)(out + e) = *(uint4*)h;
}

// ---------------------------------------------------------------------------
// Shared fp16 NT GEMM mainloop (SW128 swizzle), rolling fragment prefetch,
// loop-invariant XOR hoisted into kbx[4].
// acc = A[128,K] @ B[128,K]^T; K contiguous; 3-stage cp.async; 8 warps (2x4),
// warp tile 64x32; fp32 accumulate.
// ---------------------------------------------------------------------------
__device__ __forceinline__ void mainloop_h(
    const __half* __restrict__ A, const __half* __restrict__ B,
    int K, int lda, int ldb, uint32_t sbase,
    int tid, int lane, int wm, int wn, float acc[4][4][4])
{
    constexpr int STAGES = 3;
    constexpr uint32_t STG_BYTES = 32768;

    const __half* ga[4];
    const __half* gb[4];
    uint32_t sw[4];
#pragma unroll
    for (int i = 0; i < 4; i++) {
        const int idx = i * 256 + tid;
        const int row = idx >> 3;
        const int c   = idx & 7;
        const uint32_t off = (uint32_t)row * 128u + (uint32_t)c * 16u;
        sw[i] = off ^ ((off >> 3) & 0x70u);
        ga[i] = A + (long)row * lda + c * 8;
        gb[i] = B + (long)row * ldb + c * 8;
    }

    auto issue = [&](int kt, int st) {
        const uint32_t s0 = sbase + (uint32_t)st * STG_BYTES;
#pragma unroll
        for (int i = 0; i < 4; i++) cp16(s0 + sw[i], ga[i] + (long)kt * 64);
#pragma unroll
        for (int i = 0; i < 4; i++) cp16(s0 + 16384u + sw[i], gb[i] + (long)kt * 64);
        asm volatile("cp.async.commit_group;" ::: "memory");
    };

    const int r16 = lane & 15;
    const uint32_t hi16 = (uint32_t)(lane >> 4) * 16u;
    // The swizzle XOR value depends only on (row & 7) = (lane & 7) -> SAME
    // for every operand block. Hoist: kbx[kc] = (kc*32 + hi16) ^ x.
    const uint32_t x = ((uint32_t)(lane & 7)) << 4;
    uint32_t kbx[4];
#pragma unroll
    for (int kc = 0; kc < 4; kc++) kbx[kc] = ((uint32_t)kc * 32u + hi16) ^ x;

    uint32_t aBase[4], bBase[2];
#pragma unroll
    for (int mt = 0; mt < 4; mt++)
        aBase[mt] = (uint32_t)(wm * 64 + mt * 16 + r16) * 128u;
#pragma unroll
    for (int p = 0; p < 2; p++)
        bBase[p] = 16384u + (uint32_t)(wn * 32 + p * 16 + r16) * 128u;

    const int KT = K >> 6;
#pragma unroll
    for (int s = 0; s < STAGES - 1; s++) issue(s, s);

    for (int kt = 0; kt < KT; kt++) {
        asm volatile("cp.async.wait_group %0;" :: "n"(STAGES - 2));
        __syncthreads();

        const int pf = kt + STAGES - 1;
        if (pf < KT) issue(pf, pf % STAGES);
        else asm volatile("cp.async.commit_group;" ::: "memory");

        const uint32_t base = sbase + (uint32_t)(kt % STAGES) * STG_BYTES;

        uint32_t af[2][4];      // ping-pong by mt parity
        uint32_t bf[2][2][4];   // ping-pong by kc parity

        // preload kc=0 fragments: both B blocks + first A block
        LDSM4(bf[0][0], base + bBase[0] + kbx[0]);
        LDSM4(bf[0][1], base + bBase[1] + kbx[0]);
        LDSM4(af[0],    base + aBase[0] + kbx[0]);

#pragma unroll
        for (int kc = 0; kc < 4; kc++) {
#pragma unroll
            for (int mt = 0; mt < 4; mt++) {
                // prefetch the NEXT fragment(s) before this block's MMAs
                if (mt < 3) {
                    LDSM4(af[(mt + 1) & 1], base + aBase[mt + 1] + kbx[kc]);
                } else if (kc < 3) {
                    LDSM4(bf[(kc + 1) & 1][0], base + bBase[0] + kbx[kc + 1]);
                    LDSM4(bf[(kc + 1) & 1][1], base + bBase[1] + kbx[kc + 1]);
                    LDSM4(af[0],               base + aBase[0] + kbx[kc + 1]);
                }
#pragma unroll
                for (int nt = 0; nt < 4; nt++)
                    MMA_F16(acc[mt][nt], af[mt & 1],
                            bf[kc & 1][nt >> 1][nt & 1],
                            bf[kc & 1][nt >> 1][(nt & 1) + 2]);
            }
        }
    }
}

// ---------------------------------------------------------------------------
// Merged QKV projection: z = blockIdx.z selects (input, W, bias, output).
// z==2 (V) stores transposed per batch: Vt[(b*DD + n)*SS + s].
// ---------------------------------------------------------------------------
__global__ __launch_bounds__(256, 2)
void gemm_proj(const __half* __restrict__ Ax, const __half* __restrict__ Ay,
               const __half* __restrict__ Az, const __half* __restrict__ W,
               const float* __restrict__ b0, const float* __restrict__ b1,
               const float* __restrict__ b2,
               __half* __restrict__ Qo, __half* __restrict__ Ko,
               __half* __restrict__ Vt)
{
    extern __shared__ __align__(1024) char smem[];
    const uint32_t sbase = smem_u32(smem);
    const int tid  = threadIdx.x;
    const int lane = tid & 31;
    const int wid  = tid >> 5;
    const int wm   = wid & 1;
    const int wn   = wid >> 1;
    const int bm   = blockIdx.y * 128;
    const int bn   = blockIdx.x * 128;
    const int z    = blockIdx.z;

    const __half* A = (z == 0) ? Ax : (z == 1) ? Ay : Az;
    const __half* B = W + (long)z * DD * DD;
    const float* bias = (z == 0) ? b0 : (z == 1) ? b1 : b2;

    float acc[4][4][4];
#pragma unroll
    for (int mt = 0; mt < 4; mt++)
#pragma unroll
        for (int nt = 0; nt < 4; nt++)
#pragma unroll
            for (int i = 0; i < 4; i++) acc[mt][nt][i] = 0.0f;

    mainloop_h(A + (long)bm * DD, B + (long)bn * DD, DD, DD, DD,
               sbase, tid, lane, wm, wn, acc);

    const int g  = lane >> 2;
    const int tg = lane & 3;
#pragma unroll
    for (int mt = 0; mt < 4; mt++) {
#pragma unroll
        for (int nt = 0; nt < 4; nt++) {
            const int n = bn + wn * 32 + nt * 8 + tg * 2;
            float2 bv = *(const float2*)(bias + n);
#pragma unroll
            for (int h = 0; h < 2; h++) {
                const int m = bm + wm * 64 + mt * 16 + g + h * 8;
                const float v0 = acc[mt][nt][h * 2 + 0] + bv.x;
                const float v1 = acc[mt][nt][h * 2 + 1] + bv.y;
                if (z == 2) {
                    const int b = m >> 11;
                    const int s = m & (SS - 1);
                    const long o = ((long)b * DD + n) * SS + s;
                    Vt[o]      = __float2half_rn(v0);
                    Vt[o + SS] = __float2half_rn(v1);
                } else {
                    __half* C = (z == 0) ? Qo : Ko;
                    *(__half2*)(C + (long)m * DD + n) = __floats2half2_rn(v0, v1);
                }
            }
        }
    }
}

// ---------------------------------------------------------------------------
// Scores: P = exp(Q @ K^T / 32) (fp16, unnormalized) + atomic row sums.
// ---------------------------------------------------------------------------
__global__ __launch_bounds__(256, 2)
void gemm_scores(const __half* __restrict__ Q, const __half* __restrict__ Kb,
                 __half* __restrict__ P, float* __restrict__ RS)
{
    extern __shared__ __align__(1024) char smem[];
    const uint32_t sbase = smem_u32(smem);
    const int tid  = threadIdx.x;
    const int lane = tid & 31;
    const int wid  = tid >> 5;
    const int wm   = wid & 1;
    const int wn   = wid >> 1;
    const int bm   = blockIdx.y * 128;
    const int bn   = blockIdx.x * 128;
    const long bz  = blockIdx.z;

    const __half* A = Q  + bz * SS * DD + (long)bm * DD;
    const __half* B = Kb + bz * SS * DD + (long)bn * DD;
    __half* Pb = P + bz * (long)SS * SS;
    float* rs = RS + bz * SS;

    float acc[4][4][4];
#pragma unroll
    for (int mt = 0; mt < 4; mt++)
#pragma unroll
        for (int nt = 0; nt < 4; nt++)
#pragma unroll
            for (int i = 0; i < 4; i++) acc[mt][nt][i] = 0.0f;

    mainloop_h(A, B, DD, DD, DD, sbase, tid, lane, wm, wn, acc);

    const int g  = lane >> 2;
    const int tg = lane & 3;
#pragma unroll
    for (int mt = 0; mt < 4; mt++) {
        float s0 = 0.0f, s1 = 0.0f;
        const int m0 = bm + wm * 64 + mt * 16 + g;
#pragma unroll
        for (int nt = 0; nt < 4; nt++) {
            const int n = bn + wn * 32 + nt * 8 + tg * 2;
            const float e00 = __expf(acc[mt][nt][0] * 0.03125f);
            const float e01 = __expf(acc[mt][nt][1] * 0.03125f);
            const float e10 = __expf(acc[mt][nt][2] * 0.03125f);
            const float e11 = __expf(acc[mt][nt][3] * 0.03125f);
            s0 += e00 + e01;
            s1 += e10 + e11;
            *(__half2*)(Pb + (long)m0 * SS + n)       = __floats2half2_rn(e00, e01);
            *(__half2*)(Pb + (long)(m0 + 8) * SS + n) = __floats2half2_rn(e10, e11);
        }
        s0 += __shfl_xor_sync(~0u, s0, 1);
        s0 += __shfl_xor_sync(~0u, s0, 2);
        s1 += __shfl_xor_sync(~0u, s1, 1);
        s1 += __shfl_xor_sync(~0u, s1, 2);
        if (tg == 0) {
            atomicAdd(&rs[m0],     s0);
            atomicAdd(&rs[m0 + 8], s1);
        }
    }
}

// ---------------------------------------------------------------------------
// PV: out = (P @ Vt^T) / rowsum  (fp32 out)
// ---------------------------------------------------------------------------
__global__ __launch_bounds__(256, 2)
void gemm_pv(const __half* __restrict__ P, const __half* __restrict__ Vt,
             const float* __restrict__ RS, float* __restrict__ O)
{
    extern __shared__ __align__(1024) char smem[];
    const uint32_t sbase = smem_u32(smem);
    const int tid  = threadIdx.x;
    const int lane = tid & 31;
    const int wid  = tid >> 5;
    const int wm   = wid & 1;
    const int wn   = wid >> 1;
    const int bm   = blockIdx.y * 128;
    const int bn   = blockIdx.x * 128;
    const long bz  = blockIdx.z;

    const __half* A = P  + bz * (long)SS * SS + (long)bm * SS;
    const __half* B = Vt + bz * (long)DD * SS + (long)bn * SS;
    const float* rs = RS + bz * SS;
    float* C = O + bz * (long)SS * DD;

    float acc[4][4][4];
#pragma unroll
    for (int mt = 0; mt < 4; mt++)
#pragma unroll
        for (int nt = 0; nt < 4; nt++)
#pragma unroll
            for (int i = 0; i < 4; i++) acc[mt][nt][i] = 0.0f;

    mainloop_h(A, B, SS, SS, SS, sbase, tid, lane, wm, wn, acc);

    const int g  = lane >> 2;
    const int tg = lane & 3;
#pragma unroll
    for (int mt = 0; mt < 4; mt++) {
        const int m0 = bm + wm * 64 + mt * 16 + g;
        const float i0 = 1.0f / __ldg(&rs[m0]);
        const float i1 = 1.0f / __ldg(&rs[m0 + 8]);
#pragma unroll
        for (int nt = 0; nt < 4; nt++) {
            const int n = bn + wn * 32 + nt * 8 + tg * 2;
            float2 v0, v1;
            v0.x = acc[mt][nt][0] * i0;
            v0.y = acc[mt][nt][1] * i0;
            v1.x = acc[mt][nt][2] * i1;
            v1.y = acc[mt][nt][3] * i1;
            *(float2*)(C + (long)m0 * DD + n)       = v0;
            *(float2*)(C + (long)(m0 + 8) * DD + n) = v1;
        }
    }
}

extern "C" void kernel_launch(void* const* d_in, const int* in_sizes, int n_in,
                              void* d_out, int out_size)
{
    const float* x  = (const float*)d_in[0];
    const float* y  = (const float*)d_in[1];
    const float* z  = (const float*)d_in[2];
    const float* Wq = (const float*)d_in[3];
    const float* bq = (const float*)d_in[4];
    const float* Wk = (const float*)d_in[5];
    const float* bk = (const float*)d_in[6];
    const float* Wv = (const float*)d_in[7];
    const float* bv = (const float*)d_in[8];
    float* out = (float*)d_out;

    void *pX, *pY, *pZ, *pW, *pQ, *pK, *pV, *pP, *pRS;
    cudaGetSymbolAddress(&pX,  g_X);
    cudaGetSymbolAddress(&pY,  g_Y);
    cudaGetSymbolAddress(&pZ,  g_Z);
    cudaGetSymbolAddress(&pW,  g_W);
    cudaGetSymbolAddress(&pQ,  g_Q);
    cudaGetSymbolAddress(&pK,  g_K);
    cudaGetSymbolAddress(&pV,  g_Vt);
    cudaGetSymbolAddress(&pP,  g_P);
    cudaGetSymbolAddress(&pRS, g_RS);
    __half* X  = (__half*)pX;
    __half* Y  = (__half*)pY;
    __half* Z  = (__half*)pZ;
    __half* W  = (__half*)pW;
    __half* Q  = (__half*)pQ;
    __half* Kb = (__half*)pK;
    __half* Vt = (__half*)pV;
    __half* P  = (__half*)pP;
    float*  RS = (float*)pRS;

    const int SMEMSZ = 3 * 32768;   // 96 KB
    cudaFuncSetAttribute(gemm_proj,   cudaFuncAttributeMaxDynamicSharedMemorySize, SMEMSZ);
    cudaFuncSetAttribute(gemm_scores, cudaFuncAttributeMaxDynamicSharedMemorySize, SMEMSZ);
    cudaFuncSetAttribute(gemm_pv,     cudaFuncAttributeMaxDynamicSharedMemorySize, SMEMSZ);

    // 0) one fused conversion pass (X,Y,Z,Wq,Wk,Wv) + RS zeroing
    cvt_all<<<13824, 256>>>((const float4*)x, (const float4*)y, (const float4*)z,
                            (const float4*)Wq, (const float4*)Wk, (const float4*)Wv,
                            X, Y, Z, W, RS);
    // 1) merged QKV projections (V transposed)
    {
        dim3 g1(DD / 128, MTOT / 128, 3);
        gemm_proj<<<g1, 256, SMEMSZ>>>(X, Y, Z, W, bq, bk, bv, Q, Kb, Vt);
    }
    // 2) P = exp(Q K^T / 32), row sums via atomics
    {
        dim3 g2(SS / 128, SS / 128, BB);
        gemm_scores<<<g2, 256, SMEMSZ>>>(Q, Kb, P, RS);
    }
    // 3) out = (P @ Vt^T) / rowsum
    {
        dim3 g3(DD / 128, SS / 128, BB);
        gemm_pv<<<g3, 256, SMEMSZ>>>(P, Vt, RS, out);
    }
}

// round 13
// speedup vs baseline: 1.2174x; 1.0512x over previous
#include <cuda_runtime.h>
#include <cuda_fp16.h>
#include <cstdint>

#define BB 4
#define SS 2048
#define DD 1024
#define MTOT (BB*SS)   // 8192

// Static device scratch
__device__ __half g_X [(long)MTOT*DD];
__device__ __half g_Y [(long)MTOT*DD];
__device__ __half g_Z [(long)MTOT*DD];
__device__ __half g_W [3][(long)DD*DD];
__device__ __half g_Q [(long)MTOT*DD];
__device__ __half g_K [(long)MTOT*DD];
__device__ __half g_Vt[(long)BB*DD*SS];    // V transposed: [b][d][s]
__device__ __half g_P [(long)BB*SS*SS];    // exp(scores) fp16 (unnormalized)
__device__ float  g_RS[MTOT];              // per-row sums of exp

// Scheduling state (zeroed by cvt_all each call -> replay-safe)
__device__ int g_tick;
__device__ int g_qc[64];   // Q proj tiles done per 128-row block (need 8)
__device__ int g_kc[64];   // K proj tiles done per 128-row block (need 8)
__device__ int g_sc[64];   // score tiles done per 128-row block (need 16)
__device__ int g_vc[32];   // V proj tiles done per (batch, d-block) (need 16)

// ---------------------------------------------------------------------------
// helpers
// ---------------------------------------------------------------------------
__device__ __forceinline__ uint32_t smem_u32(const void* p) {
    uint32_t a;
    asm("{ .reg .u64 t; cvta.to.shared.u64 t, %1; cvt.u32.u64 %0, t; }"
        : "=r"(a) : "l"(p));
    return a;
}
__device__ __forceinline__ void cp16(uint32_t s, const void* g) {
    asm volatile("cp.async.cg.shared.global [%0], [%1], 16;" :: "r"(s), "l"(g));
}

#define LDSM4(r, addr) \
    asm volatile("ldmatrix.sync.aligned.m8n8.x4.shared.b16 {%0,%1,%2,%3}, [%4];" \
        : "=r"((r)[0]), "=r"((r)[1]), "=r"((r)[2]), "=r"((r)[3]) : "r"(addr))

#define MMA_F16(c, a, b0, b1) \
    asm volatile("mma.sync.aligned.m16n8k16.row.col.f32.f16.f16.f32 " \
        "{%0,%1,%2,%3}, {%4,%5,%6,%7}, {%8,%9}, {%0,%1,%2,%3};" \
        : "+f"((c)[0]), "+f"((c)[1]), "+f"((c)[2]), "+f"((c)[3]) \
        : "r"((a)[0]), "r"((a)[1]), "r"((a)[2]), "r"((a)[3]), "r"(b0), "r"(b1))

// ---------------------------------------------------------------------------
// Fused fp32->fp16 conversion for X,Y,Z,Wq,Wk,Wv + RS/scheduler zeroing.
// ---------------------------------------------------------------------------
__global__ void cvt_all(const float4* __restrict__ x, const float4* __restrict__ y,
                        const float4* __restrict__ z, const float4* __restrict__ wq,
                        const float4* __restrict__ wk, const float4* __restrict__ wv,
                        __half* __restrict__ X, __half* __restrict__ Y,
                        __half* __restrict__ Z, __half* __restrict__ W,
                        float* __restrict__ rs)
{
    const int b = blockIdx.x;
    const int tid = threadIdx.x;

    if (b < 32) rs[b * 256 + tid] = 0.0f;
    if (b == 0) {
        if (tid == 0) g_tick = 0;
        else if (tid < 65)  g_qc[tid - 1]   = 0;
        else if (tid < 129) g_kc[tid - 65]  = 0;
        else if (tid < 193) g_sc[tid - 129] = 0;
        else if (tid < 225) g_vc[tid - 193] = 0;
    }

    const float4* in;
    __half* out;
    long base;
    if (b < 4096)       { in = x;  out = X; base = (long)b * 2048; }
    else if (b < 8192)  { in = y;  out = Y; base = (long)(b - 4096) * 2048; }
    else if (b < 12288) { in = z;  out = Z; base = (long)(b - 8192) * 2048; }
    else if (b < 12800) { in = wq; out = W;                       base = (long)(b - 12288) * 2048; }
    else if (b < 13312) { in = wk; out = W + (long)DD * DD;       base = (long)(b - 12800) * 2048; }
    else                { in = wv; out = W + 2 * (long)DD * DD;   base = (long)(b - 13312) * 2048; }

    const long e = base + (long)tid * 8;
    float4 a0 = in[e >> 2], a1 = in[(e >> 2) + 1];
    __half2 h[4];
    h[0] = __floats2half2_rn(a0.x, a0.y);
    h[1] = __floats2half2_rn(a0.z, a0.w);
    h[2] = __floats2half2_rn(a1.x, a1.y);
    h[3] = __floats2half2_rn(a1.z, a1.w);
    *(uint4*)(out + e) = *(uint4*)h;
}

// ---------------------------------------------------------------------------
// fp16 NT GEMM mainloop (SW128, rolling fragment prefetch, hoisted XOR).
// Entry __syncthreads protects smem reuse across tiles in the persistent loop.
// ---------------------------------------------------------------------------
__device__ __forceinline__ void mainloop_h(
    const __half* __restrict__ A, const __half* __restrict__ B,
    int K, int lda, int ldb, uint32_t sbase,
    int tid, int lane, int wm, int wn, float acc[4][4][4])
{
    constexpr int STAGES = 3;
    constexpr uint32_t STG_BYTES = 32768;

    const __half* ga[4];
    const __half* gb[4];
    uint32_t sw[4];
#pragma unroll
    for (int i = 0; i < 4; i++) {
        const int idx = i * 256 + tid;
        const int row = idx >> 3;
        const int c   = idx & 7;
        const uint32_t off = (uint32_t)row * 128u + (uint32_t)c * 16u;
        sw[i] = off ^ ((off >> 3) & 0x70u);
        ga[i] = A + (long)row * lda + c * 8;
        gb[i] = B + (long)row * ldb + c * 8;
    }

    auto issue = [&](int kt, int st) {
        const uint32_t s0 = sbase + (uint32_t)st * STG_BYTES;
#pragma unroll
        for (int i = 0; i < 4; i++) cp16(s0 + sw[i], ga[i] + (long)kt * 64);
#pragma unroll
        for (int i = 0; i < 4; i++) cp16(s0 + 16384u + sw[i], gb[i] + (long)kt * 64);
        asm volatile("cp.async.commit_group;" ::: "memory");
    };

    const int r16 = lane & 15;
    const uint32_t hi16 = (uint32_t)(lane >> 4) * 16u;
    const uint32_t x = ((uint32_t)(lane & 7)) << 4;
    uint32_t kbx[4];
#pragma unroll
    for (int kc = 0; kc < 4; kc++) kbx[kc] = ((uint32_t)kc * 32u + hi16) ^ x;

    uint32_t aBase[4], bBase[2];
#pragma unroll
    for (int mt = 0; mt < 4; mt++)
        aBase[mt] = (uint32_t)(wm * 64 + mt * 16 + r16) * 128u;
#pragma unroll
    for (int p = 0; p < 2; p++)
        bBase[p] = 16384u + (uint32_t)(wn * 32 + p * 16 + r16) * 128u;

    __syncthreads();   // previous tile's smem readers are done

    const int KT = K >> 6;
#pragma unroll
    for (int s = 0; s < STAGES - 1; s++) issue(s, s);

    for (int kt = 0; kt < KT; kt++) {
        asm volatile("cp.async.wait_group %0;" :: "n"(STAGES - 2));
        __syncthreads();

        const int pf = kt + STAGES - 1;
        if (pf < KT) issue(pf, pf % STAGES);
        else asm volatile("cp.async.commit_group;" ::: "memory");

        const uint32_t base = sbase + (uint32_t)(kt % STAGES) * STG_BYTES;

        uint32_t af[2][4];
        uint32_t bf[2][2][4];

        LDSM4(bf[0][0], base + bBase[0] + kbx[0]);
        LDSM4(bf[0][1], base + bBase[1] + kbx[0]);
        LDSM4(af[0],    base + aBase[0] + kbx[0]);

#pragma unroll
        for (int kc = 0; kc < 4; kc++) {
#pragma unroll
            for (int mt = 0; mt < 4; mt++) {
                if (mt < 3) {
                    LDSM4(af[(mt + 1) & 1], base + aBase[mt + 1] + kbx[kc]);
                } else if (kc < 3) {
                    LDSM4(bf[(kc + 1) & 1][0], base + bBase[0] + kbx[kc + 1]);
                    LDSM4(bf[(kc + 1) & 1][1], base + bBase[1] + kbx[kc + 1]);
                    LDSM4(af[0],               base + aBase[0] + kbx[kc + 1]);
                }
#pragma unroll
                for (int nt = 0; nt < 4; nt++)
                    MMA_F16(acc[mt][nt], af[mt & 1],
                            bf[kc & 1][nt >> 1][nt & 1],
                            bf[kc & 1][nt >> 1][(nt & 1) + 2]);
            }
        }
    }
}

// ---------------------------------------------------------------------------
// Persistent mega-kernel: tickets 0-511 Qproj, 512-1023 Kproj, 1024-1535
// Vproj, 1536-2559 scores, 2560-3071 PV. Dependencies via atomic counters.
// Deadlock-free: every gate depends only on strictly lower tickets.
// ---------------------------------------------------------------------------
__global__ __launch_bounds__(256, 2)
void attn_mega(const __half* __restrict__ X, const __half* __restrict__ Y,
               const __half* __restrict__ Z, const __half* __restrict__ W,
               const float* __restrict__ bq, const float* __restrict__ bk,
               const float* __restrict__ bv,
               __half* __restrict__ Q, __half* __restrict__ Kb,
               __half* __restrict__ Vt, __half* __restrict__ P,
               float* __restrict__ RS, float* __restrict__ O)
{
    extern __shared__ __align__(1024) char smem[];
    __shared__ int s_t;
    const uint32_t sbase = smem_u32(smem);
    const int tid  = threadIdx.x;
    const int lane = tid & 31;
    const int wid  = tid >> 5;
    const int wm   = wid & 1;
    const int wn   = wid >> 1;
    const int g    = lane >> 2;
    const int tg   = lane & 3;

    for (;;) {
        if (tid == 0) s_t = atomicAdd(&g_tick, 1);
        __syncthreads();
        const int t = s_t;
        if (t >= 3072) break;

        float acc[4][4][4];
#pragma unroll
        for (int mt = 0; mt < 4; mt++)
#pragma unroll
            for (int nt = 0; nt < 4; nt++)
#pragma unroll
                for (int i = 0; i < 4; i++) acc[mt][nt][i] = 0.0f;

        if (t < 1536) {
            // ---------------- projection tile ----------------
            const int z   = t >> 9;
            const int rem = t & 511;
            const int bm  = (rem >> 3) * 128;
            const int bn  = (rem & 7) * 128;
            const __half* A = ((z == 0) ? X : (z == 1) ? Y : Z) + (long)bm * DD;
            const __half* B = W + (long)z * DD * DD + (long)bn * DD;
            mainloop_h(A, B, DD, DD, DD, sbase, tid, lane, wm, wn, acc);

            const float* bias = (z == 0) ? bq : (z == 1) ? bk : bv;
#pragma unroll
            for (int mt = 0; mt < 4; mt++) {
#pragma unroll
                for (int nt = 0; nt < 4; nt++) {
                    const int n = bn + wn * 32 + nt * 8 + tg * 2;
                    float2 bv2 = *(const float2*)(bias + n);
#pragma unroll
                    for (int h = 0; h < 2; h++) {
                        const int m = bm + wm * 64 + mt * 16 + g + h * 8;
                        const float v0 = acc[mt][nt][h * 2 + 0] + bv2.x;
                        const float v1 = acc[mt][nt][h * 2 + 1] + bv2.y;
                        if (z == 2) {
                            const int b = m >> 11;
                            const int s = m & (SS - 1);
                            const long o = ((long)b * DD + n) * SS + s;
                            Vt[o]      = __float2half_rn(v0);
                            Vt[o + SS] = __float2half_rn(v1);
                        } else {
                            __half* C = (z == 0) ? Q : Kb;
                            *(__half2*)(C + (long)m * DD + n) = __floats2half2_rn(v0, v1);
                        }
                    }
                }
            }
            __threadfence();
            __syncthreads();
            if (tid == 0) {
                if (z == 0)      atomicAdd(&g_qc[rem >> 3], 1);
                else if (z == 1) atomicAdd(&g_kc[rem >> 3], 1);
                else             atomicAdd(&g_vc[((rem >> 3) >> 4) * 8 + (rem & 7)], 1);
            }
        } else if (t < 2560) {
            // ---------------- scores tile ----------------
            const int s   = t - 1536;
            const int bz  = s >> 8;
            const int bml = (s >> 4) & 15;
            const int bnl = s & 15;
            if (tid == 0) {
                while (atomicAdd(&g_qc[bz * 16 + bml], 0) < 8) __nanosleep(128);
                while (atomicAdd(&g_kc[bz * 16 + bnl], 0) < 8) __nanosleep(128);
                __threadfence();
            }
            const int bm = bml * 128;
            const int bn = bnl * 128;
            const __half* A = Q  + (long)bz * SS * DD + (long)bm * DD;
            const __half* B = Kb + (long)bz * SS * DD + (long)bn * DD;
            mainloop_h(A, B, DD, DD, DD, sbase, tid, lane, wm, wn, acc);

            __half* Pb = P + (long)bz * SS * SS;
            float* rs = RS + bz * SS;
#pragma unroll
            for (int mt = 0; mt < 4; mt++) {
                float s0 = 0.0f, s1 = 0.0f;
                const int m0 = bm + wm * 64 + mt * 16 + g;
#pragma unroll
                for (int nt = 0; nt < 4; nt++) {
                    const int n = bn + wn * 32 + nt * 8 + tg * 2;
                    const float e00 = __expf(acc[mt][nt][0] * 0.03125f);
                    const float e01 = __expf(acc[mt][nt][1] * 0.03125f);
                    const float e10 = __expf(acc[mt][nt][2] * 0.03125f);
                    const float e11 = __expf(acc[mt][nt][3] * 0.03125f);
                    s0 += e00 + e01;
                    s1 += e10 + e11;
                    *(__half2*)(Pb + (long)m0 * SS + n)       = __floats2half2_rn(e00, e01);
                    *(__half2*)(Pb + (long)(m0 + 8) * SS + n) = __floats2half2_rn(e10, e11);
                }
                s0 += __shfl_xor_sync(~0u, s0, 1);
                s0 += __shfl_xor_sync(~0u, s0, 2);
                s1 += __shfl_xor_sync(~0u, s1, 1);
                s1 += __shfl_xor_sync(~0u, s1, 2);
                if (tg == 0) {
                    atomicAdd(&rs[m0],     s0);
                    atomicAdd(&rs[m0 + 8], s1);
                }
            }
            __threadfence();
            __syncthreads();
            if (tid == 0) atomicAdd(&g_sc[bz * 16 + bml], 1);
        } else {
            // ---------------- PV tile ----------------
            const int p   = t - 2560;
            const int bz  = p >> 7;
            const int bml = (p >> 3) & 15;
            const int bnl = p & 7;
            if (tid == 0) {
                while (atomicAdd(&g_sc[bz * 16 + bml], 0) < 16) __nanosleep(128);
                while (atomicAdd(&g_vc[bz * 8 + bnl],  0) < 16) __nanosleep(128);
                __threadfence();
            }
            const int bm = bml * 128;
            const int bn = bnl * 128;
            const __half* A = P  + (long)bz * SS * SS + (long)bm * SS;
            const __half* B = Vt + (long)bz * DD * SS + (long)bn * SS;
            mainloop_h(A, B, SS, SS, SS, sbase, tid, lane, wm, wn, acc);

            const float* rs = RS + bz * SS;
            float* C = O + (long)bz * SS * DD;
#pragma unroll
            for (int mt = 0; mt < 4; mt++) {
                const int m0 = bm + wm * 64 + mt * 16 + g;
                const float i0 = 1.0f / __ldg(&rs[m0]);
                const float i1 = 1.0f / __ldg(&rs[m0 + 8]);
#pragma unroll
                for (int nt = 0; nt < 4; nt++) {
                    const int n = bn + wn * 32 + nt * 8 + tg * 2;
                    float2 v0, v1;
                    v0.x = acc[mt][nt][0] * i0;
                    v0.y = acc[mt][nt][1] * i0;
                    v1.x = acc[mt][nt][2] * i1;
                    v1.y = acc[mt][nt][3] * i1;
                    *(float2*)(C + (long)m0 * DD + n)       = v0;
                    *(float2*)(C + (long)(m0 + 8) * DD + n) = v1;
                }
            }
        }
    }
}

extern "C" void kernel_launch(void* const* d_in, const int* in_sizes, int n_in,
                              void* d_out, int out_size)
{
    const float* x  = (const float*)d_in[0];
    const float* y  = (const float*)d_in[1];
    const float* z  = (const float*)d_in[2];
    const float* Wq = (const float*)d_in[3];
    const float* bq = (const float*)d_in[4];
    const float* Wk = (const float*)d_in[5];
    const float* bk = (const float*)d_in[6];
    const float* Wv = (const float*)d_in[7];
    const float* bv = (const float*)d_in[8];
    float* out = (float*)d_out;

    void *pX, *pY, *pZ, *pW, *pQ, *pK, *pV, *pP, *pRS;
    cudaGetSymbolAddress(&pX,  g_X);
    cudaGetSymbolAddress(&pY,  g_Y);
    cudaGetSymbolAddress(&pZ,  g_Z);
    cudaGetSymbolAddress(&pW,  g_W);
    cudaGetSymbolAddress(&pQ,  g_Q);
    cudaGetSymbolAddress(&pK,  g_K);
    cudaGetSymbolAddress(&pV,  g_Vt);
    cudaGetSymbolAddress(&pP,  g_P);
    cudaGetSymbolAddress(&pRS, g_RS);
    __half* X  = (__half*)pX;
    __half* Y  = (__half*)pY;
    __half* Z  = (__half*)pZ;
    __half* W  = (__half*)pW;
    __half* Q  = (__half*)pQ;
    __half* Kb = (__half*)pK;
    __half* Vt = (__half*)pV;
    __half* P  = (__half*)pP;
    float*  RS = (float*)pRS;

    int nsm = 148;
    cudaDeviceGetAttribute(&nsm, cudaDevAttrMultiProcessorCount, 0);

    const int SMEMSZ = 3 * 32768;   // 96 KB
    cudaFuncSetAttribute(attn_mega, cudaFuncAttributeMaxDynamicSharedMemorySize, SMEMSZ);

    // 0) conversions + scheduler/RS zeroing
    cvt_all<<<13824, 256>>>((const float4*)x, (const float4*)y, (const float4*)z,
                            (const float4*)Wq, (const float4*)Wk, (const float4*)Wv,
                            X, Y, Z, W, RS);
    // 1) persistent fused proj + scores + PV
    attn_mega<<<2 * nsm, 256, SMEMSZ>>>(X, Y, Z, W, bq, bk, bv,
                                        Q, Kb, Vt, P, RS, out);
}